// round 5
// baseline (speedup 1.0000x reference)
#include <cuda_runtime.h>
#include <math.h>

#define BATCH 8
#define NPTS  32768
#define NSEG  32
#define KIN   22
#define CATS  40
#define TILE  64
#define SUBT  4
#define LDSE  68          // 64 points + pad; 272B row stride keeps 16B alignment
#define SEGLD 161         // odd stride -> segment rows hit distinct banks
#define NTHREADS 512
#define CTAS_PER_B (NPTS / (TILE*SUBT))   // 128
#define NCTA (BATCH * CTAS_PER_B)         // 1024

typedef unsigned long long ull;

// packed f32x2 helpers (sm_103a; ptxas emits FFMA2 only via PTX fma.rn.f32x2)
#define PACK2(out, f)   asm("mov.b64 %0, {%1, %1};" : "=l"(out) : "f"(f))
#define UNPACK2(lo, hi, v) asm("mov.b64 {%0, %1}, %2;" : "=f"(lo), "=f"(hi) : "l"(v))
#define FMA2(d, a, b, c) asm("fma.rn.f32x2 %0, %1, %2, %3;" : "=l"(d) : "l"(a), "l"(b), "l"(c))

// ---------------- scratch (static device memory; no allocations) ----------------
__device__ float    g_f[(size_t)BATCH * 128 * NPTS];   // 128 MB ping buffer (reused in-place)
__device__ unsigned g_seg0[BATCH * NSEG * 160];
__device__ unsigned g_seg1[BATCH * NSEG * 160];
__device__ float    g_cf0[BATCH * NSEG * 128];
__device__ float    g_cf1[BATCH * NSEG * 128];
__device__ unsigned g_net[BATCH * 128];

// monotonic float<->uint encoding for atomicMax on floats
__device__ __forceinline__ unsigned encf(float f) {
    unsigned u = __float_as_uint(f);
    return (u & 0x80000000u) ? ~u : (u | 0x80000000u);
}
__device__ __forceinline__ float decf(unsigned e) {
    return (e & 0x80000000u) ? __uint_as_float(e ^ 0x80000000u) : __uint_as_float(~e);
}

// ---------------- fused conv layer: out[co][p] = relu(W[co,:] . in[:,p] + b[co]) ----
// 512 threads. COUT>=64: 8 pts/thread, 64 channel groups, J=COUT/64.
// COUT==32: 4 pts/thread, 32 channel groups, J=1 (all threads active).
template<int CIN, int COUT>
__device__ __forceinline__ void layer_gemm(const float* __restrict__ W,
                                           const float* __restrict__ bias,
                                           const float* __restrict__ in,
                                           float* __restrict__ out, int t)
{
    constexpr int PTS = (COUT >= 64) ? 8 : 4;      // points per thread
    constexpr int NP  = TILE / PTS;                // point groups (8 or 16)
    constexpr int NC  = NTHREADS / NP;             // channel groups (64 or 32)
    constexpr int J   = COUT / NC;                 // 1,2,4
    constexpr int QW  = PTS / 2;                   // f32x2 pairs per point set
    const int pg = t & (NP - 1);
    const int cg = t / NP;

    ull acc[J][QW];
#pragma unroll
    for (int j = 0; j < J; ++j) {
        float bv = __ldg(&bias[cg + NC * j]);
        ull bb; PACK2(bb, bv);
#pragma unroll
        for (int q = 0; q < QW; ++q) acc[j][q] = bb;
    }
    if constexpr ((CIN & 3) == 0) {
#pragma unroll 2
        for (int ci = 0; ci < CIN; ci += 4) {
            ull a[4][QW];
#pragma unroll
            for (int u = 0; u < 4; ++u) {
                const ulonglong2* row =
                    reinterpret_cast<const ulonglong2*>(in + (ci + u) * LDSE) + pg * (QW / 2);
                ulonglong2 r0 = row[0];
                a[u][0] = r0.x; a[u][1] = r0.y;
                if constexpr (QW == 4) {
                    ulonglong2 r1 = row[1];
                    a[u][2] = r1.x; a[u][3] = r1.y;
                }
            }
#pragma unroll
            for (int j = 0; j < J; ++j) {
                float4 w4 = __ldg(reinterpret_cast<const float4*>(W + (cg + NC * j) * CIN + ci));
                ull w0, w1, w2, w3;
                PACK2(w0, w4.x); PACK2(w1, w4.y); PACK2(w2, w4.z); PACK2(w3, w4.w);
#pragma unroll
                for (int q = 0; q < QW; ++q) {
                    FMA2(acc[j][q], w0, a[0][q], acc[j][q]);
                    FMA2(acc[j][q], w1, a[1][q], acc[j][q]);
                    FMA2(acc[j][q], w2, a[2][q], acc[j][q]);
                    FMA2(acc[j][q], w3, a[3][q], acc[j][q]);
                }
            }
        }
    } else {
#pragma unroll 2
        for (int ci = 0; ci < CIN; ++ci) {
            const ulonglong2* row =
                reinterpret_cast<const ulonglong2*>(in + ci * LDSE) + pg * (QW / 2);
            ulonglong2 r0 = row[0];
            ull a0 = r0.x, a1 = r0.y, a2 = 0, a3 = 0;
            if constexpr (QW == 4) {
                ulonglong2 r1 = row[1];
                a2 = r1.x; a3 = r1.y;
            }
#pragma unroll
            for (int j = 0; j < J; ++j) {
                float w = __ldg(&W[(cg + NC * j) * CIN + ci]);
                ull ww; PACK2(ww, w);
                FMA2(acc[j][0], ww, a0, acc[j][0]);
                FMA2(acc[j][1], ww, a1, acc[j][1]);
                if constexpr (QW == 4) {
                    FMA2(acc[j][2], ww, a2, acc[j][2]);
                    FMA2(acc[j][3], ww, a3, acc[j][3]);
                }
            }
        }
    }
#pragma unroll
    for (int j = 0; j < J; ++j) {
        float* orow = out + (cg + NC * j) * LDSE + pg * PTS;
#pragma unroll
        for (int q = 0; q < QW; ++q) {
            float lo, hi;
            UNPACK2(lo, hi, acc[j][q]);
            orow[2 * q]     = fmaxf(lo, 0.0f);
            orow[2 * q + 1] = fmaxf(hi, 0.0f);
        }
    }
    __syncthreads();
}

// smem layout: bufA(128 rows) | bufB(256 rows) | seg | idx
#define SM_BUFA 0
#define SM_BUFB (128 * LDSE)
#define SM_SEG  ((128 + 256) * LDSE)
#define SM_IDX  (SM_SEG + NSEG * SEGLD)

// ---------------- init ----------------
__global__ void init_kernel() {
    int i = blockIdx.x * 256 + threadIdx.x;
    unsigned NEG = encf(-1e30f);
    if (i < BATCH * NSEG * 160) { g_seg0[i] = NEG; g_seg1[i] = NEG; }
    if (i < BATCH * 128) g_net[i] = NEG;
}

// ---------------- Pass A: input conv + block0 convs + corr + segmax ----------------
extern "C" __global__ void __launch_bounds__(NTHREADS, 1)
passA_kernel(const float* __restrict__ feat, const int* __restrict__ clus,
             const float* __restrict__ w_in, const float* __restrict__ b_in,
             const float* __restrict__ w1, const float* __restrict__ b1,
             const float* __restrict__ w2, const float* __restrict__ b2,
             const float* __restrict__ wc1, const float* __restrict__ bc1,
             const float* __restrict__ wc2, const float* __restrict__ bc2,
             const float* __restrict__ wc3, const float* __restrict__ bc3)
{
    extern __shared__ float sm[];
    float* bufA = sm + SM_BUFA;
    float* bufB = sm + SM_BUFB;
    unsigned* seg = reinterpret_cast<unsigned*>(sm + SM_SEG);
    int* idxs = reinterpret_cast<int*>(sm + SM_IDX);
    const int t = threadIdx.x;
    const int b = blockIdx.x / CTAS_PER_B;
    const int n0 = (blockIdx.x % CTAS_PER_B) * (TILE * SUBT);
    const unsigned NEG = encf(-1e30f);

    for (int i = t; i < NSEG * SEGLD; i += NTHREADS) seg[i] = NEG;
    __syncthreads();

    for (int sub = 0; sub < SUBT; ++sub) {
        const int nb = n0 + sub * TILE;
        if (t < TILE) idxs[t] = __ldg(&clus[(size_t)b * NPTS + nb + t]);
        for (int i = t; i < KIN * TILE; i += NTHREADS) {
            int k = i / TILE, p = i % TILE;
            bufA[k * LDSE + p] = feat[((size_t)b * NPTS + nb + p) * KIN + k];
        }
        __syncthreads();
        layer_gemm<KIN, 256>(w_in, b_in, bufA, bufB, t);   // f256 -> B
        layer_gemm<256, 64>(w1, b1, bufB, bufA, t);        // f64  -> A
        layer_gemm<64, 128>(w2, b2, bufA, bufB, t);        // f128 -> B
        // store f128 + feature segmax
        for (int i = t; i < 128 * TILE; i += NTHREADS) {
            int c = i >> 6, p = i & 63;
            float v = bufB[c * LDSE + p];
            g_f[((size_t)b * 128 + c) * NPTS + nb + p] = v;
            atomicMax(&seg[idxs[p] * SEGLD + c], encf(v));
        }
        layer_gemm<128, 128>(wc1, bc1, bufB, bufA, t);     // corr chain
        layer_gemm<128, 256>(wc2, bc2, bufA, bufB, t);
        layer_gemm<256, 32>(wc3, bc3, bufB, bufA, t);
        for (int i = t; i < NSEG * TILE; i += NTHREADS) {
            int c = i >> 6, p = i & 63;
            atomicMax(&seg[idxs[p] * SEGLD + 128 + c], encf(bufA[c * LDSE + p]));
        }
        __syncthreads();
    }
    for (int i = t; i < NSEG * 160; i += NTHREADS) {
        int s = i / 160, c = i % 160;
        atomicMax(&g_seg0[((size_t)b * NSEG + s) * 160 + c], seg[s * SEGLD + c]);
    }
}

// ---------------- cluster math (per batch, tiny): corrM + cf' ----------------
__global__ void cluster_kernel(int phase) {
    const unsigned* gs = phase ? g_seg1 : g_seg0;
    float* gcf = phase ? g_cf1 : g_cf0;
    int b = blockIdx.x, t = threadIdx.x;
    __shared__ float cf[128][NSEG + 1];
    __shared__ float cm[NSEG][NSEG + 1];
    __shared__ float corrM[NSEG][NSEG + 1];
    for (int i = t; i < NSEG * 160; i += 256) {
        int s = i / 160, c = i % 160;
        float v = fmaxf(decf(gs[((size_t)b * NSEG + s) * 160 + c]), -100.0f);
        if (c < 128) cf[c][s] = v; else cm[s][c - 128] = v;
    }
    __syncthreads();
    if (t < NSEG) {
        float ss = 0.f;
        for (int j = 0; j < NSEG; ++j) ss += cm[t][j] * cm[t][j];
        float inv = 1.0f / fmaxf(sqrtf(ss), 1e-12f);
        for (int j = 0; j < NSEG; ++j) cm[t][j] *= inv;
    }
    __syncthreads();
    for (int i = t; i < NSEG * NSEG; i += 256) {
        int s1 = i >> 5, s2 = i & 31;
        float d = 0.f;
        for (int j = 0; j < NSEG; ++j) d = fmaf(cm[s1][j], cm[s2][j], d);
        corrM[s1][s2] = d;
    }
    __syncthreads();
    for (int i = t; i < NSEG * 128; i += 256) {
        int s = i >> 7, ch = i & 127;
        float d = 0.f;
        for (int s2 = 0; s2 < NSEG; ++s2) d = fmaf(cf[ch][s2], corrM[s2][s], d);
        gcf[((size_t)b * NSEG + s) * 128 + ch] = d;  // [b][seg][ch] for gather
    }
}

// ---------------- Pass C: w3_0 + pool0 gather + block1 convs + corr + segmax ----------------
extern "C" __global__ void __launch_bounds__(NTHREADS, 1)
passC_kernel(const int* __restrict__ clus0, const int* __restrict__ clus1,
             const float* __restrict__ w3_0, const float* __restrict__ b3_0,
             const float* __restrict__ w1_1, const float* __restrict__ b1_1,
             const float* __restrict__ w2_1, const float* __restrict__ b2_1,
             const float* __restrict__ wc1, const float* __restrict__ bc1,
             const float* __restrict__ wc2, const float* __restrict__ bc2,
             const float* __restrict__ wc3, const float* __restrict__ bc3)
{
    extern __shared__ float sm[];
    float* bufA = sm + SM_BUFA;
    float* bufB = sm + SM_BUFB;
    unsigned* seg = reinterpret_cast<unsigned*>(sm + SM_SEG);
    int* idx0 = reinterpret_cast<int*>(sm + SM_IDX);
    int* idx1 = idx0 + TILE;
    const int t = threadIdx.x;
    const int b = blockIdx.x / CTAS_PER_B;
    const int n0 = (blockIdx.x % CTAS_PER_B) * (TILE * SUBT);
    const unsigned NEG = encf(-1e30f);

    for (int i = t; i < NSEG * SEGLD; i += NTHREADS) seg[i] = NEG;
    __syncthreads();

    for (int sub = 0; sub < SUBT; ++sub) {
        const int nb = n0 + sub * TILE;
        if (t < TILE) {
            idx0[t] = __ldg(&clus0[(size_t)b * NPTS + nb + t]);
            idx1[t] = __ldg(&clus1[(size_t)b * NPTS + nb + t]);
        }
        for (int i = t; i < 128 * TILE; i += NTHREADS) {  // load f128 tile
            int c = i >> 6, p = i & 63;
            bufA[c * LDSE + p] = g_f[((size_t)b * 128 + c) * NPTS + nb + p];
        }
        __syncthreads();
        layer_gemm<128, 128>(w3_0, b3_0, bufA, bufB, t);   // f_w3 -> B rows 0..127
        for (int i = t; i < 128 * TILE; i += NTHREADS) {   // gather pool0 -> B rows 128..255
            int ch = i & 127, p = i >> 7;
            bufB[(128 + ch) * LDSE + p] = g_cf0[((size_t)b * NSEG + idx0[p]) * 128 + ch];
        }
        __syncthreads();
        layer_gemm<256, 64>(w1_1, b1_1, bufB, bufA, t);
        layer_gemm<64, 128>(w2_1, b2_1, bufA, bufB, t);    // g128 -> B
        for (int i = t; i < 128 * TILE; i += NTHREADS) {   // in-place store + segmax
            int c = i >> 6, p = i & 63;
            float v = bufB[c * LDSE + p];
            g_f[((size_t)b * 128 + c) * NPTS + nb + p] = v;
            atomicMax(&seg[idx1[p] * SEGLD + c], encf(v));
        }
        layer_gemm<128, 128>(wc1, bc1, bufB, bufA, t);
        layer_gemm<128, 256>(wc2, bc2, bufA, bufB, t);
        layer_gemm<256, 32>(wc3, bc3, bufB, bufA, t);
        for (int i = t; i < NSEG * TILE; i += NTHREADS) {
            int c = i >> 6, p = i & 63;
            atomicMax(&seg[idx1[p] * SEGLD + 128 + c], encf(bufA[c * LDSE + p]));
        }
        __syncthreads();
    }
    for (int i = t; i < NSEG * 160; i += NTHREADS) {
        int s = i / 160, c = i % 160;
        atomicMax(&g_seg1[((size_t)b * NSEG + s) * 160 + c], seg[s * SEGLD + c]);
    }
}

// ---------------- Pass E: w3_1 + pool1 gather + output convs + global max ----------------
extern "C" __global__ void __launch_bounds__(NTHREADS, 1)
passE_kernel(const int* __restrict__ clus1,
             const float* __restrict__ w3_1, const float* __restrict__ b3_1,
             const float* __restrict__ w_out1, const float* __restrict__ b_out1,
             const float* __restrict__ w_out2, const float* __restrict__ b_out2)
{
    extern __shared__ float sm[];
    float* bufA = sm + SM_BUFA;
    float* bufB = sm + SM_BUFB;
    unsigned* netm = reinterpret_cast<unsigned*>(sm + SM_SEG);
    int* idx1 = reinterpret_cast<int*>(sm + SM_IDX);
    const int t = threadIdx.x;
    const int b = blockIdx.x / CTAS_PER_B;
    const int n0 = (blockIdx.x % CTAS_PER_B) * (TILE * SUBT);
    const unsigned NEG = encf(-1e30f);

    if (t < 128) netm[t] = NEG;
    __syncthreads();

    for (int sub = 0; sub < SUBT; ++sub) {
        const int nb = n0 + sub * TILE;
        if (t < TILE) idx1[t] = __ldg(&clus1[(size_t)b * NPTS + nb + t]);
        for (int i = t; i < 128 * TILE; i += NTHREADS) {  // load g128 tile
            int c = i >> 6, p = i & 63;
            bufA[c * LDSE + p] = g_f[((size_t)b * 128 + c) * NPTS + nb + p];
        }
        __syncthreads();
        layer_gemm<128, 128>(w3_1, b3_1, bufA, bufB, t);
        for (int i = t; i < 128 * TILE; i += NTHREADS) {  // gather pool1
            int ch = i & 127, p = i >> 7;
            bufB[(128 + ch) * LDSE + p] = g_cf1[((size_t)b * NSEG + idx1[p]) * 128 + ch];
        }
        __syncthreads();
        layer_gemm<256, 128>(w_out1, b_out1, bufB, bufA, t);
        layer_gemm<128, 128>(w_out2, b_out2, bufA, bufB, t);
        if (t < 128) {                                    // per-channel max over this tile
            float m = -1e30f;
            for (int p = 0; p < TILE; ++p) m = fmaxf(m, bufB[t * LDSE + p]);
            unsigned e = encf(m);
            if (e > netm[t]) netm[t] = e;
        }
        __syncthreads();
    }
    if (t < 128) atomicMax(&g_net[b * 128 + t], netm[t]);
}

// ---------------- dense head ----------------
__global__ void dense_kernel(const float* __restrict__ dw1, const float* __restrict__ db1,
                             const float* __restrict__ dw2, const float* __restrict__ db2,
                             const float* __restrict__ dw3, const float* __restrict__ db3,
                             float* __restrict__ out)
{
    __shared__ float net[BATCH * 128];
    __shared__ float h1[BATCH * 256];
    __shared__ float h2[BATCH * 256];
    int t = threadIdx.x;
    for (int i = t; i < BATCH * 128; i += 256) net[i] = decf(g_net[i]);
    __syncthreads();
    for (int i = t; i < BATCH * 256; i += 256) {
        int b = i >> 8, o = i & 255;
        float s = db1[o];
        for (int k = 0; k < 128; ++k) s = fmaf(net[b * 128 + k], dw1[k * 256 + o], s);
        h1[i] = (s >= 0.f) ? s : 0.2f * s;
    }
    __syncthreads();
    for (int i = t; i < BATCH * 256; i += 256) {
        int b = i >> 8, o = i & 255;
        float s = db2[o];
        for (int k = 0; k < 256; ++k) s = fmaf(h1[b * 256 + k], dw2[k * 256 + o], s);
        h2[i] = (s >= 0.f) ? s : 0.2f * s;
    }
    __syncthreads();
    for (int i = t; i < BATCH * CATS; i += 256) {
        int b = i / CATS, o = i % CATS;
        float s = db3[o];
        for (int k = 0; k < 256; ++k) s = fmaf(h2[b * 256 + k], dw3[k * CATS + o], s);
        out[b * CATS + o] = s;
    }
}

// ---------------- launch ----------------
extern "C" void kernel_launch(void* const* d_in, const int* in_sizes, int n_in,
                              void* d_out, int out_size)
{
    const float* feat   = (const float*)d_in[0];
    const int*   clus   = (const int*)  d_in[1];
    const float* w_in   = (const float*)d_in[2];
    const float* b_in   = (const float*)d_in[3];
    const float* w1     = (const float*)d_in[4];
    const float* b1     = (const float*)d_in[5];
    const float* w2     = (const float*)d_in[6];
    const float* b2     = (const float*)d_in[7];
    const float* w3     = (const float*)d_in[8];
    const float* b3     = (const float*)d_in[9];
    const float* wc1    = (const float*)d_in[10];
    const float* bc1    = (const float*)d_in[11];
    const float* wc2    = (const float*)d_in[12];
    const float* bc2    = (const float*)d_in[13];
    const float* wc3    = (const float*)d_in[14];
    const float* bc3    = (const float*)d_in[15];
    const float* w_out1 = (const float*)d_in[16];
    const float* b_out1 = (const float*)d_in[17];
    const float* w_out2 = (const float*)d_in[18];
    const float* b_out2 = (const float*)d_in[19];
    const float* dw1    = (const float*)d_in[20];
    const float* db1    = (const float*)d_in[21];
    const float* dw2    = (const float*)d_in[22];
    const float* db2    = (const float*)d_in[23];
    const float* dw3    = (const float*)d_in[24];
    const float* db3    = (const float*)d_in[25];

    const size_t SMEM = (size_t)(SM_IDX + 2 * TILE + 32) * sizeof(float);
    cudaFuncSetAttribute(passA_kernel, cudaFuncAttributeMaxDynamicSharedMemorySize, (int)SMEM);
    cudaFuncSetAttribute(passC_kernel, cudaFuncAttributeMaxDynamicSharedMemorySize, (int)SMEM);
    cudaFuncSetAttribute(passE_kernel, cudaFuncAttributeMaxDynamicSharedMemorySize, (int)SMEM);

    init_kernel<<<(BATCH * NSEG * 160 + 255) / 256, 256>>>();

    passA_kernel<<<NCTA, NTHREADS, SMEM>>>(feat, clus, w_in, b_in, w1, b1, w2, b2,
                                           wc1, bc1, wc2, bc2, wc3, bc3);
    cluster_kernel<<<BATCH, 256>>>(0);

    passC_kernel<<<NCTA, NTHREADS, SMEM>>>(clus, clus + (size_t)BATCH * NPTS,
                                           w3, b3,
                                           w1 + 64 * 256, b1 + 64,
                                           w2 + 128 * 64, b2 + 128,
                                           wc1 + 128 * 128, bc1 + 128,
                                           wc2 + 256 * 128, bc2 + 256,
                                           wc3 + 32 * 256, bc3 + 32);
    cluster_kernel<<<BATCH, 256>>>(1);

    passE_kernel<<<NCTA, NTHREADS, SMEM>>>(clus + (size_t)BATCH * NPTS,
                                           w3 + 128 * 128, b3 + 128,
                                           w_out1, b_out1, w_out2, b_out2);

    dense_kernel<<<1, 256>>>(dw1, db1, dw2, db2, dw3, db3, (float*)d_out);
}

// round 10
// speedup vs baseline: 1.8856x; 1.8856x over previous
#include <cuda_runtime.h>
#include <math.h>

#define BATCH 8
#define NPTS  32768
#define NSEG  32
#define KIN   22
#define CATS  40
#define TILE  64
#define SUBT  4
#define LDSE  68          // 64 points + pad; 272B row stride keeps 16B alignment
#define SEGLD 161         // odd stride -> segment rows hit distinct banks
#define NTHREADS 256
#define CTAS_PER_B (NPTS / (TILE*SUBT))   // 128
#define NCTA (BATCH * CTAS_PER_B)         // 1024

typedef unsigned long long ull;

// packed f32x2 helpers (sm_103a; ptxas emits FFMA2 only via PTX fma.rn.f32x2)
#define PACK2(out, f)   asm("mov.b64 %0, {%1, %1};" : "=l"(out) : "f"(f))
#define UNPACK2(lo, hi, v) asm("mov.b64 {%0, %1}, %2;" : "=f"(lo), "=f"(hi) : "l"(v))
#define FMA2(d, a, b, c) asm("fma.rn.f32x2 %0, %1, %2, %3;" : "=l"(d) : "l"(a), "l"(b), "l"(c))

// ---------------- scratch (static device memory; no allocations) ----------------
__device__ float    g_f[(size_t)BATCH * 128 * NPTS];   // 128 MB ping buffer (reused in-place)
__device__ unsigned g_seg0[BATCH * NSEG * 160];
__device__ unsigned g_seg1[BATCH * NSEG * 160];
__device__ float    g_cf0[BATCH * NSEG * 128];
__device__ float    g_cf1[BATCH * NSEG * 128];
__device__ unsigned g_net[BATCH * 128];

// monotonic float<->uint encoding for atomicMax on floats
__device__ __forceinline__ unsigned encf(float f) {
    unsigned u = __float_as_uint(f);
    return (u & 0x80000000u) ? ~u : (u | 0x80000000u);
}
__device__ __forceinline__ float decf(unsigned e) {
    return (e & 0x80000000u) ? __uint_as_float(e ^ 0x80000000u) : __uint_as_float(~e);
}

// ---------------- fused conv layer: out[co][p] = relu(W[co,:] . in[:,p] + b[co]) ----
// 256 threads. Mapping: 16 point-groups x 16 channel-groups.
// Thread t: pg = t&15 (4 points, 2 f32x2 pairs), cg = t>>4, J = COUT/16 channels.
// High J => each delivered activation byte feeds J FMAs (kills L1 redundancy).
template<int CIN, int COUT>
__device__ __forceinline__ void layer_gemm(const float* __restrict__ W,
                                           const float* __restrict__ bias,
                                           const float* __restrict__ in,
                                           float* __restrict__ out, int t)
{
    constexpr int NC = 16;
    constexpr int J  = COUT / NC;     // 16, 8, 4, 2
    const int pg = t & 15;
    const int cg = t >> 4;

    ull acc[J][2];
#pragma unroll
    for (int j = 0; j < J; ++j) {
        float bv = __ldg(&bias[cg + NC * j]);
        ull bb; PACK2(bb, bv);
        acc[j][0] = bb; acc[j][1] = bb;
    }
    if constexpr ((CIN & 3) == 0) {
#pragma unroll 2
        for (int ci = 0; ci < CIN; ci += 4) {
            ull a[4][2];
#pragma unroll
            for (int u = 0; u < 4; ++u) {
                ulonglong2 r =
                    reinterpret_cast<const ulonglong2*>(in + (ci + u) * LDSE)[pg];
                a[u][0] = r.x; a[u][1] = r.y;
            }
#pragma unroll
            for (int j = 0; j < J; ++j) {
                float4 w4 = __ldg(reinterpret_cast<const float4*>(W + (cg + NC * j) * CIN + ci));
                ull w0, w1, w2, w3;
                PACK2(w0, w4.x); PACK2(w1, w4.y); PACK2(w2, w4.z); PACK2(w3, w4.w);
                FMA2(acc[j][0], w0, a[0][0], acc[j][0]);
                FMA2(acc[j][1], w0, a[0][1], acc[j][1]);
                FMA2(acc[j][0], w1, a[1][0], acc[j][0]);
                FMA2(acc[j][1], w1, a[1][1], acc[j][1]);
                FMA2(acc[j][0], w2, a[2][0], acc[j][0]);
                FMA2(acc[j][1], w2, a[2][1], acc[j][1]);
                FMA2(acc[j][0], w3, a[3][0], acc[j][0]);
                FMA2(acc[j][1], w3, a[3][1], acc[j][1]);
            }
        }
    } else {
#pragma unroll 2
        for (int ci = 0; ci < CIN; ++ci) {
            ulonglong2 r = reinterpret_cast<const ulonglong2*>(in + ci * LDSE)[pg];
            ull a0 = r.x, a1 = r.y;
#pragma unroll
            for (int j = 0; j < J; ++j) {
                float w = __ldg(&W[(cg + NC * j) * CIN + ci]);
                ull ww; PACK2(ww, w);
                FMA2(acc[j][0], ww, a0, acc[j][0]);
                FMA2(acc[j][1], ww, a1, acc[j][1]);
            }
        }
    }
#pragma unroll
    for (int j = 0; j < J; ++j) {
        float* orow = out + (cg + NC * j) * LDSE + pg * 4;
        float lo, hi;
        UNPACK2(lo, hi, acc[j][0]);
        orow[0] = fmaxf(lo, 0.0f);
        orow[1] = fmaxf(hi, 0.0f);
        UNPACK2(lo, hi, acc[j][1]);
        orow[2] = fmaxf(lo, 0.0f);
        orow[3] = fmaxf(hi, 0.0f);
    }
    __syncthreads();
}

// smem layout: bufA(128 rows) | bufB(256 rows) | seg | idx
#define SM_BUFA 0
#define SM_BUFB (128 * LDSE)
#define SM_SEG  ((128 + 256) * LDSE)
#define SM_IDX  (SM_SEG + NSEG * SEGLD)

// ---------------- init ----------------
__global__ void init_kernel() {
    int i = blockIdx.x * 256 + threadIdx.x;
    unsigned NEG = encf(-1e30f);
    if (i < BATCH * NSEG * 160) { g_seg0[i] = NEG; g_seg1[i] = NEG; }
    if (i < BATCH * 128) g_net[i] = NEG;
}

// ---------------- Pass A: input conv + block0 convs + corr + segmax ----------------
extern "C" __global__ void __launch_bounds__(NTHREADS, 1)
passA_kernel(const float* __restrict__ feat, const int* __restrict__ clus,
             const float* __restrict__ w_in, const float* __restrict__ b_in,
             const float* __restrict__ w1, const float* __restrict__ b1,
             const float* __restrict__ w2, const float* __restrict__ b2,
             const float* __restrict__ wc1, const float* __restrict__ bc1,
             const float* __restrict__ wc2, const float* __restrict__ bc2,
             const float* __restrict__ wc3, const float* __restrict__ bc3)
{
    extern __shared__ float sm[];
    float* bufA = sm + SM_BUFA;
    float* bufB = sm + SM_BUFB;
    unsigned* seg = reinterpret_cast<unsigned*>(sm + SM_SEG);
    int* idxs = reinterpret_cast<int*>(sm + SM_IDX);
    const int t = threadIdx.x;
    const int b = blockIdx.x / CTAS_PER_B;
    const int n0 = (blockIdx.x % CTAS_PER_B) * (TILE * SUBT);
    const unsigned NEG = encf(-1e30f);

    for (int i = t; i < NSEG * SEGLD; i += NTHREADS) seg[i] = NEG;
    __syncthreads();

    for (int sub = 0; sub < SUBT; ++sub) {
        const int nb = n0 + sub * TILE;
        if (t < TILE) idxs[t] = __ldg(&clus[(size_t)b * NPTS + nb + t]);
        for (int i = t; i < KIN * TILE; i += NTHREADS) {
            int k = i / TILE, p = i % TILE;
            bufA[k * LDSE + p] = feat[((size_t)b * NPTS + nb + p) * KIN + k];
        }
        __syncthreads();
        layer_gemm<KIN, 256>(w_in, b_in, bufA, bufB, t);   // f256 -> B
        layer_gemm<256, 64>(w1, b1, bufB, bufA, t);        // f64  -> A
        layer_gemm<64, 128>(w2, b2, bufA, bufB, t);        // f128 -> B
        // store f128 + feature segmax
        for (int i = t; i < 128 * TILE; i += NTHREADS) {
            int c = i >> 6, p = i & 63;
            float v = bufB[c * LDSE + p];
            g_f[((size_t)b * 128 + c) * NPTS + nb + p] = v;
            atomicMax(&seg[idxs[p] * SEGLD + c], encf(v));
        }
        layer_gemm<128, 128>(wc1, bc1, bufB, bufA, t);     // corr chain
        layer_gemm<128, 256>(wc2, bc2, bufA, bufB, t);
        layer_gemm<256, 32>(wc3, bc3, bufB, bufA, t);
        for (int i = t; i < NSEG * TILE; i += NTHREADS) {
            int c = i >> 6, p = i & 63;
            atomicMax(&seg[idxs[p] * SEGLD + 128 + c], encf(bufA[c * LDSE + p]));
        }
        __syncthreads();
    }
    for (int i = t; i < NSEG * 160; i += NTHREADS) {
        int s = i / 160, c = i % 160;
        atomicMax(&g_seg0[((size_t)b * NSEG + s) * 160 + c], seg[s * SEGLD + c]);
    }
}

// ---------------- cluster math (per batch, tiny): corrM + cf' ----------------
__global__ void cluster_kernel(int phase) {
    const unsigned* gs = phase ? g_seg1 : g_seg0;
    float* gcf = phase ? g_cf1 : g_cf0;
    int b = blockIdx.x, t = threadIdx.x;
    __shared__ float cf[128][NSEG + 1];
    __shared__ float cm[NSEG][NSEG + 1];
    __shared__ float corrM[NSEG][NSEG + 1];
    for (int i = t; i < NSEG * 160; i += 256) {
        int s = i / 160, c = i % 160;
        float v = fmaxf(decf(gs[((size_t)b * NSEG + s) * 160 + c]), -100.0f);
        if (c < 128) cf[c][s] = v; else cm[s][c - 128] = v;
    }
    __syncthreads();
    if (t < NSEG) {
        float ss = 0.f;
        for (int j = 0; j < NSEG; ++j) ss += cm[t][j] * cm[t][j];
        float inv = 1.0f / fmaxf(sqrtf(ss), 1e-12f);
        for (int j = 0; j < NSEG; ++j) cm[t][j] *= inv;
    }
    __syncthreads();
    for (int i = t; i < NSEG * NSEG; i += 256) {
        int s1 = i >> 5, s2 = i & 31;
        float d = 0.f;
        for (int j = 0; j < NSEG; ++j) d = fmaf(cm[s1][j], cm[s2][j], d);
        corrM[s1][s2] = d;
    }
    __syncthreads();
    for (int i = t; i < NSEG * 128; i += 256) {
        int s = i >> 7, ch = i & 127;
        float d = 0.f;
        for (int s2 = 0; s2 < NSEG; ++s2) d = fmaf(cf[ch][s2], corrM[s2][s], d);
        gcf[((size_t)b * NSEG + s) * 128 + ch] = d;  // [b][seg][ch] for gather
    }
}

// ---------------- Pass C: w3_0 + pool0 gather + block1 convs + corr + segmax ----------------
extern "C" __global__ void __launch_bounds__(NTHREADS, 1)
passC_kernel(const int* __restrict__ clus0, const int* __restrict__ clus1,
             const float* __restrict__ w3_0, const float* __restrict__ b3_0,
             const float* __restrict__ w1_1, const float* __restrict__ b1_1,
             const float* __restrict__ w2_1, const float* __restrict__ b2_1,
             const float* __restrict__ wc1, const float* __restrict__ bc1,
             const float* __restrict__ wc2, const float* __restrict__ bc2,
             const float* __restrict__ wc3, const float* __restrict__ bc3)
{
    extern __shared__ float sm[];
    float* bufA = sm + SM_BUFA;
    float* bufB = sm + SM_BUFB;
    unsigned* seg = reinterpret_cast<unsigned*>(sm + SM_SEG);
    int* idx0 = reinterpret_cast<int*>(sm + SM_IDX);
    int* idx1 = idx0 + TILE;
    const int t = threadIdx.x;
    const int b = blockIdx.x / CTAS_PER_B;
    const int n0 = (blockIdx.x % CTAS_PER_B) * (TILE * SUBT);
    const unsigned NEG = encf(-1e30f);

    for (int i = t; i < NSEG * SEGLD; i += NTHREADS) seg[i] = NEG;
    __syncthreads();

    for (int sub = 0; sub < SUBT; ++sub) {
        const int nb = n0 + sub * TILE;
        if (t < TILE) {
            idx0[t] = __ldg(&clus0[(size_t)b * NPTS + nb + t]);
            idx1[t] = __ldg(&clus1[(size_t)b * NPTS + nb + t]);
        }
        for (int i = t; i < 128 * TILE; i += NTHREADS) {  // load f128 tile
            int c = i >> 6, p = i & 63;
            bufA[c * LDSE + p] = g_f[((size_t)b * 128 + c) * NPTS + nb + p];
        }
        __syncthreads();
        layer_gemm<128, 128>(w3_0, b3_0, bufA, bufB, t);   // f_w3 -> B rows 0..127
        for (int i = t; i < 128 * TILE; i += NTHREADS) {   // gather pool0 -> B rows 128..255
            int ch = i & 127, p = i >> 7;
            bufB[(128 + ch) * LDSE + p] = g_cf0[((size_t)b * NSEG + idx0[p]) * 128 + ch];
        }
        __syncthreads();
        layer_gemm<256, 64>(w1_1, b1_1, bufB, bufA, t);
        layer_gemm<64, 128>(w2_1, b2_1, bufA, bufB, t);    // g128 -> B
        for (int i = t; i < 128 * TILE; i += NTHREADS) {   // in-place store + segmax
            int c = i >> 6, p = i & 63;
            float v = bufB[c * LDSE + p];
            g_f[((size_t)b * 128 + c) * NPTS + nb + p] = v;
            atomicMax(&seg[idx1[p] * SEGLD + c], encf(v));
        }
        layer_gemm<128, 128>(wc1, bc1, bufB, bufA, t);
        layer_gemm<128, 256>(wc2, bc2, bufA, bufB, t);
        layer_gemm<256, 32>(wc3, bc3, bufB, bufA, t);
        for (int i = t; i < NSEG * TILE; i += NTHREADS) {
            int c = i >> 6, p = i & 63;
            atomicMax(&seg[idx1[p] * SEGLD + 128 + c], encf(bufA[c * LDSE + p]));
        }
        __syncthreads();
    }
    for (int i = t; i < NSEG * 160; i += NTHREADS) {
        int s = i / 160, c = i % 160;
        atomicMax(&g_seg1[((size_t)b * NSEG + s) * 160 + c], seg[s * SEGLD + c]);
    }
}

// ---------------- Pass E: w3_1 + pool1 gather + output convs + global max ----------------
extern "C" __global__ void __launch_bounds__(NTHREADS, 1)
passE_kernel(const int* __restrict__ clus1,
             const float* __restrict__ w3_1, const float* __restrict__ b3_1,
             const float* __restrict__ w_out1, const float* __restrict__ b_out1,
             const float* __restrict__ w_out2, const float* __restrict__ b_out2)
{
    extern __shared__ float sm[];
    float* bufA = sm + SM_BUFA;
    float* bufB = sm + SM_BUFB;
    unsigned* netm = reinterpret_cast<unsigned*>(sm + SM_SEG);
    int* idx1 = reinterpret_cast<int*>(sm + SM_IDX);
    const int t = threadIdx.x;
    const int b = blockIdx.x / CTAS_PER_B;
    const int n0 = (blockIdx.x % CTAS_PER_B) * (TILE * SUBT);
    const unsigned NEG = encf(-1e30f);

    if (t < 128) netm[t] = NEG;
    __syncthreads();

    for (int sub = 0; sub < SUBT; ++sub) {
        const int nb = n0 + sub * TILE;
        if (t < TILE) idx1[t] = __ldg(&clus1[(size_t)b * NPTS + nb + t]);
        for (int i = t; i < 128 * TILE; i += NTHREADS) {  // load g128 tile
            int c = i >> 6, p = i & 63;
            bufA[c * LDSE + p] = g_f[((size_t)b * 128 + c) * NPTS + nb + p];
        }
        __syncthreads();
        layer_gemm<128, 128>(w3_1, b3_1, bufA, bufB, t);
        for (int i = t; i < 128 * TILE; i += NTHREADS) {  // gather pool1
            int ch = i & 127, p = i >> 7;
            bufB[(128 + ch) * LDSE + p] = g_cf1[((size_t)b * NSEG + idx1[p]) * 128 + ch];
        }
        __syncthreads();
        layer_gemm<256, 128>(w_out1, b_out1, bufB, bufA, t);
        layer_gemm<128, 128>(w_out2, b_out2, bufA, bufB, t);
        if (t < 128) {                                    // per-channel max over this tile
            float m = -1e30f;
            for (int p = 0; p < TILE; ++p) m = fmaxf(m, bufB[t * LDSE + p]);
            unsigned e = encf(m);
            if (e > netm[t]) netm[t] = e;
        }
        __syncthreads();
    }
    if (t < 128) atomicMax(&g_net[b * 128 + t], netm[t]);
}

// ---------------- dense head ----------------
__global__ void dense_kernel(const float* __restrict__ dw1, const float* __restrict__ db1,
                             const float* __restrict__ dw2, const float* __restrict__ db2,
                             const float* __restrict__ dw3, const float* __restrict__ db3,
                             float* __restrict__ out)
{
    __shared__ float net[BATCH * 128];
    __shared__ float h1[BATCH * 256];
    __shared__ float h2[BATCH * 256];
    int t = threadIdx.x;
    for (int i = t; i < BATCH * 128; i += 256) net[i] = decf(g_net[i]);
    __syncthreads();
    for (int i = t; i < BATCH * 256; i += 256) {
        int b = i >> 8, o = i & 255;
        float s = db1[o];
        for (int k = 0; k < 128; ++k) s = fmaf(net[b * 128 + k], dw1[k * 256 + o], s);
        h1[i] = (s >= 0.f) ? s : 0.2f * s;
    }
    __syncthreads();
    for (int i = t; i < BATCH * 256; i += 256) {
        int b = i >> 8, o = i & 255;
        float s = db2[o];
        for (int k = 0; k < 256; ++k) s = fmaf(h1[b * 256 + k], dw2[k * 256 + o], s);
        h2[i] = (s >= 0.f) ? s : 0.2f * s;
    }
    __syncthreads();
    for (int i = t; i < BATCH * CATS; i += 256) {
        int b = i / CATS, o = i % CATS;
        float s = db3[o];
        for (int k = 0; k < 256; ++k) s = fmaf(h2[b * 256 + k], dw3[k * CATS + o], s);
        out[b * CATS + o] = s;
    }
}

// ---------------- launch ----------------
extern "C" void kernel_launch(void* const* d_in, const int* in_sizes, int n_in,
                              void* d_out, int out_size)
{
    const float* feat   = (const float*)d_in[0];
    const int*   clus   = (const int*)  d_in[1];
    const float* w_in   = (const float*)d_in[2];
    const float* b_in   = (const float*)d_in[3];
    const float* w1     = (const float*)d_in[4];
    const float* b1     = (const float*)d_in[5];
    const float* w2     = (const float*)d_in[6];
    const float* b2     = (const float*)d_in[7];
    const float* w3     = (const float*)d_in[8];
    const float* b3     = (const float*)d_in[9];
    const float* wc1    = (const float*)d_in[10];
    const float* bc1    = (const float*)d_in[11];
    const float* wc2    = (const float*)d_in[12];
    const float* bc2    = (const float*)d_in[13];
    const float* wc3    = (const float*)d_in[14];
    const float* bc3    = (const float*)d_in[15];
    const float* w_out1 = (const float*)d_in[16];
    const float* b_out1 = (const float*)d_in[17];
    const float* w_out2 = (const float*)d_in[18];
    const float* b_out2 = (const float*)d_in[19];
    const float* dw1    = (const float*)d_in[20];
    const float* db1    = (const float*)d_in[21];
    const float* dw2    = (const float*)d_in[22];
    const float* db2    = (const float*)d_in[23];
    const float* dw3    = (const float*)d_in[24];
    const float* db3    = (const float*)d_in[25];

    const size_t SMEM = (size_t)(SM_IDX + 2 * TILE + 32) * sizeof(float);
    cudaFuncSetAttribute(passA_kernel, cudaFuncAttributeMaxDynamicSharedMemorySize, (int)SMEM);
    cudaFuncSetAttribute(passC_kernel, cudaFuncAttributeMaxDynamicSharedMemorySize, (int)SMEM);
    cudaFuncSetAttribute(passE_kernel, cudaFuncAttributeMaxDynamicSharedMemorySize, (int)SMEM);

    init_kernel<<<(BATCH * NSEG * 160 + 255) / 256, 256>>>();

    passA_kernel<<<NCTA, NTHREADS, SMEM>>>(feat, clus, w_in, b_in, w1, b1, w2, b2,
                                           wc1, bc1, wc2, bc2, wc3, bc3);
    cluster_kernel<<<BATCH, 256>>>(0);

    passC_kernel<<<NCTA, NTHREADS, SMEM>>>(clus, clus + (size_t)BATCH * NPTS,
                                           w3, b3,
                                           w1 + 64 * 256, b1 + 64,
                                           w2 + 128 * 64, b2 + 128,
                                           wc1 + 128 * 128, bc1 + 128,
                                           wc2 + 256 * 128, bc2 + 256,
                                           wc3 + 32 * 256, bc3 + 32);
    cluster_kernel<<<BATCH, 256>>>(1);

    passE_kernel<<<NCTA, NTHREADS, SMEM>>>(clus + (size_t)BATCH * NPTS,
                                           w3 + 128 * 128, b3 + 128,
                                           w_out1, b_out1, w_out2, b_out2);

    dense_kernel<<<1, 256>>>(dw1, db1, dw2, db2, dw3, db3, (float*)d_out);
}